// round 3
// baseline (speedup 1.0000x reference)
#include <cuda_runtime.h>
#include <cstdint>
#include <cstddef>

// ---------------------------------------------------------------------------
// VQ-VAE bottleneck, GB300 sm_103a.
// B=32, C=128, H=W=64 -> N=131072 positions, D=64, K=512 codes.
// This version BIT-REPLICATES the fp32 reference numerics:
//   - GEMMs: serial-k FFMA chains (acc=0, ascending k) == cublas sgemm rounding
//   - row norms: XLA warp row-reduce tree (x_l^2 + x_{l+32}^2, butterfly 16..1)
//   - dists = fl(fl(A+B) - 2*M), argmin lexicographic (tie -> lowest index)
//   - straight-through: qst = fl(z + fl(q - z)) feeds the post conv
// ---------------------------------------------------------------------------

#define NPOS   131072
#define EMB    64
#define NCODE  512
#define NHID   128

__device__ __align__(16) float g_zt[EMB * NPOS];   // z transposed: [d][n]
__device__ __align__(16) float g_wt[NHID * EMB];   // pre_w  transposed: [c][o]
__device__ __align__(16) float g_pt[EMB * NHID];   // post_w transposed: [d][o]
__device__ __align__(16) float g_ct[EMB * NCODE];  // codebook transposed: [d][k]
__device__ float g_rown[NPOS];                     // ||z_n||^2 (XLA tree)
__device__ float g_norm[NCODE];                    // ||e_k||^2 (XLA tree)
__device__ int   g_counts[NCODE];
__device__ float g_sumsq;

typedef unsigned long long ull;

__device__ __forceinline__ void ffma2(ull &d, const ull a, const ull b) {
    asm("fma.rn.f32x2 %0, %1, %2, %0;" : "+l"(d) : "l"(a), "l"(b));
}
__device__ __forceinline__ ull dup2(float v) {
    ull r; unsigned int u = __float_as_uint(v);
    asm("mov.b64 %0, {%1, %1};" : "=l"(r) : "r"(u));
    return r;
}
__device__ __forceinline__ float2 unpack2(ull p) {
    float2 f;
    asm("mov.b64 {%0, %1}, %2;" : "=f"(f.x), "=f"(f.y) : "l"(p));
    return f;
}

// ---------------- init: transposes + zeroing ----------------
__global__ void vq_init(const float* __restrict__ pre_w,
                        const float* __restrict__ post_w,
                        const float* __restrict__ cb) {
    int g = blockIdx.x * blockDim.x + threadIdx.x;
    int gs = gridDim.x * blockDim.x;
    for (int i = g; i < NHID * EMB; i += gs) {          // wt[c][o] = pre_w[o][c]
        int k = i >> 6, o = i & 63;
        g_wt[i] = pre_w[o * NHID + k];
    }
    for (int i = g; i < EMB * NHID; i += gs) {          // pt[d][o] = post_w[o][d]
        int d = i >> 7, o = i & 127;
        g_pt[i] = post_w[o * EMB + d];
    }
    for (int i = g; i < EMB * NCODE; i += gs) {         // ct[d][k] = cb[k][d]
        int d = i >> 9, k = i & 511;
        g_ct[i] = cb[k * EMB + d];
    }
    for (int i = g; i < NCODE; i += gs) g_counts[i] = 0;
    if (g == 0) g_sumsq = 0.f;
}

// ---------------- pre 1x1 conv: z[n][o], serial-c FFMA chain ----------------
__global__ void __launch_bounds__(256) vq_pre(const float* __restrict__ enc,
                                              const float* __restrict__ pre_b) {
    extern __shared__ float sm[];
    float* As = sm;            // [128 c][128 n]
    float* Ws = sm + 16384;    // [128 c][64 o]
    const int tid = threadIdx.x;
    const int tx = tid & 15, ty = tid >> 4;
    const int n0 = blockIdx.x * 128;
    const int b  = n0 >> 12;
    const int hw0 = n0 & 4095;

    const float4* enc4 = (const float4*)enc;
    float4* As4 = (float4*)As;
    float4* Ws4 = (float4*)Ws;
    for (int i = tid; i < 4096; i += 256) {
        int c = i >> 5, x = i & 31;
        As4[i] = enc4[(size_t)(b * NHID + c) * 1024 + (hw0 >> 2) + x];
    }
    for (int i = tid; i < 2048; i += 256) Ws4[i] = ((const float4*)g_wt)[i];
    __syncthreads();

    ull acc[4][4];
    #pragma unroll
    for (int i = 0; i < 4; i++)
        #pragma unroll
        for (int j = 0; j < 4; j++) acc[i][j] = 0ULL;

    #pragma unroll 4
    for (int k = 0; k < NHID; k++) {
        ulonglong2 a0 = *(const ulonglong2*)(As + k * 128 + tx * 4);
        ulonglong2 a1 = *(const ulonglong2*)(As + k * 128 + 64 + tx * 4);
        float4 w = Ws4[k * 16 + ty];
        ull ap[4] = {a0.x, a0.y, a1.x, a1.y};
        ull wd[4] = {dup2(w.x), dup2(w.y), dup2(w.z), dup2(w.w)};
        #pragma unroll
        for (int ip = 0; ip < 4; ip++)
            #pragma unroll
            for (int j = 0; j < 4; j++)
                ffma2(acc[ip][j], ap[ip], wd[j]);
    }

    #pragma unroll
    for (int j = 0; j < 4; j++) {
        int o = ty * 4 + j;
        float bias = __ldg(pre_b + o);
        float2 p0 = unpack2(acc[0][j]), p1 = unpack2(acc[1][j]);
        float4 v0 = make_float4(__fadd_rn(p0.x, bias), __fadd_rn(p0.y, bias),
                                __fadd_rn(p1.x, bias), __fadd_rn(p1.y, bias));
        *(float4*)(g_zt + (size_t)o * NPOS + n0 + tx * 4) = v0;
        float2 p2 = unpack2(acc[2][j]), p3 = unpack2(acc[3][j]);
        float4 v1 = make_float4(__fadd_rn(p2.x, bias), __fadd_rn(p2.y, bias),
                                __fadd_rn(p3.x, bias), __fadd_rn(p3.y, bias));
        *(float4*)(g_zt + (size_t)o * NPOS + n0 + 64 + tx * 4) = v1;
    }
}

// ---------------- row norms, XLA warp-tree replication ----------------
// A[n] = tree(z[n][l]^2 + z[n][l+32]^2), butterfly 16,8,4,2,1 (all __fadd_rn)
// B[k] = same tree over codebook rows.
__global__ void __launch_bounds__(256) vq_norms(const float* __restrict__ cb) {
    __shared__ float zsm[64 * 33];
    const int blk = blockIdx.x;
    const int tid = threadIdx.x;
    const int w = tid >> 5, l = tid & 31;
    if (blk < 4096) {
        const int n0 = blk * 32;
        for (int i = tid; i < 2048; i += 256) {
            int d = i >> 5, nn = i & 31;
            zsm[d * 33 + nn] = g_zt[(size_t)d * NPOS + n0 + nn];
        }
        __syncthreads();
        #pragma unroll
        for (int it = 0; it < 4; it++) {
            int nn = w + it * 8;
            float x = zsm[l * 33 + nn];
            float y = zsm[(l + 32) * 33 + nn];
            float p = __fadd_rn(__fmul_rn(x, x), __fmul_rn(y, y));
            #pragma unroll
            for (int s = 16; s > 0; s >>= 1)
                p = __fadd_rn(p, __shfl_down_sync(0xffffffffu, p, s));
            if (l == 0) g_rown[n0 + nn] = p;
        }
    } else {
        int base_k = (blk - 4096) * 16 + w * 2;
        #pragma unroll
        for (int kq = 0; kq < 2; kq++) {
            int k = base_k + kq;
            float x = cb[k * 64 + l];
            float y = cb[k * 64 + l + 32];
            float p = __fadd_rn(__fmul_rn(x, x), __fmul_rn(y, y));
            #pragma unroll
            for (int s = 16; s > 0; s >>= 1)
                p = __fadd_rn(p, __shfl_down_sync(0xffffffffu, p, s));
            if (l == 0) g_norm[k] = p;
        }
    }
}

// ---------------- main: dists + argmin + loss + hist + post conv ----------------
__global__ void __launch_bounds__(256) vq_main(const float* __restrict__ cb,
                                               const float* __restrict__ post_b,
                                               float* __restrict__ dec,
                                               float* __restrict__ idxout) {
    extern __shared__ float sm[];
    float* Zs = sm;                 // [64 d][128 n]
    float* Es = sm + 8192;          // [64 d][128 k]  (later: Ps [64 d][128 o])
    float* Qs = sm + 16384;         // [64 d][128 n]  (later: qst)
    float* norms_s = sm + 24576;    // 512  (B)
    int*   idx_s = (int*)(sm + 25088); // 128
    float* An_s = sm + 25216;       // 128  (A)

    const int tid = threadIdx.x;
    const int tx = tid & 15, ty = tid >> 4;
    const int n0 = blockIdx.x * 128;
    const int b  = n0 >> 12;
    const int hw0 = n0 & 4095;

    for (int i = tid; i < 2048; i += 256) {
        int d = i >> 5, x = i & 31;
        ((float4*)Zs)[i] = ((const float4*)g_zt)[(size_t)d * (NPOS >> 2) + (n0 >> 2) + x];
    }
    for (int i = tid; i < NCODE; i += 256) norms_s[i] = g_norm[i];
    for (int i = tid; i < 128; i += 256) An_s[i] = g_rown[n0 + i];
    __syncthreads();

    // per-thread A values, matching best[] row mapping
    float an[8];
    #pragma unroll
    for (int m = 0; m < 8; m++)
        an[m] = An_s[(m < 4) ? (ty * 4 + m) : (64 + ty * 4 + (m - 4))];

    float best[8];
    int bidx[8];
    #pragma unroll
    for (int i = 0; i < 8; i++) { best[i] = 3.4e38f; bidx[i] = 0; }

    for (int kk = 0; kk < 4; kk++) {
        __syncthreads();
        for (int i = tid; i < 2048; i += 256) {
            int d = i >> 5, x = i & 31;
            ((float4*)Es)[i] = ((const float4*)g_ct)[d * 128 + kk * 32 + x];
        }
        __syncthreads();

        ull acc[4][8];
        #pragma unroll
        for (int ip = 0; ip < 4; ip++)
            #pragma unroll
            for (int j = 0; j < 8; j++) acc[ip][j] = 0ULL;

        #pragma unroll 4
        for (int d = 0; d < EMB; d++) {
            ulonglong2 z0 = *(const ulonglong2*)(Zs + d * 128 + ty * 4);
            ulonglong2 z1 = *(const ulonglong2*)(Zs + d * 128 + 64 + ty * 4);
            float4 e0 = ((float4*)Es)[d * 32 + tx];
            float4 e1 = ((float4*)Es)[d * 32 + 16 + tx];
            ull zp[4] = {z0.x, z0.y, z1.x, z1.y};
            ull ed[8] = {dup2(e0.x), dup2(e0.y), dup2(e0.z), dup2(e0.w),
                         dup2(e1.x), dup2(e1.y), dup2(e1.z), dup2(e1.w)};
            #pragma unroll
            for (int ip = 0; ip < 4; ip++)
                #pragma unroll
                for (int j = 0; j < 8; j++)
                    ffma2(acc[ip][j], zp[ip], ed[j]);
        }

        // d = fl(fl(A + B) - 2*M)  — intrinsics prevent FMA contraction
        #pragma unroll
        for (int j = 0; j < 8; j++) {
            int k = kk * 128 + ((j < 4) ? (tx * 4 + j) : (64 + tx * 4 + j - 4));
            float Bk = norms_s[k];
            #pragma unroll
            for (int ip = 0; ip < 4; ip++) {
                float2 dd = unpack2(acc[ip][j]);
                int i0 = ip * 2;
                float dv0 = __fsub_rn(__fadd_rn(an[i0], Bk), __fmul_rn(2.0f, dd.x));
                if (dv0 < best[i0]) { best[i0] = dv0; bidx[i0] = k; }
                float dv1 = __fsub_rn(__fadd_rn(an[i0 + 1], Bk), __fmul_rn(2.0f, dd.y));
                if (dv1 < best[i0 + 1]) { best[i0 + 1] = dv1; bidx[i0 + 1] = k; }
            }
        }
    }

    // lexicographic argmin across the 16 tx lanes sharing each row
    #pragma unroll
    for (int i = 0; i < 8; i++) {
        float bd = best[i]; int bk = bidx[i];
        #pragma unroll
        for (int off = 1; off < 16; off <<= 1) {
            float od = __shfl_xor_sync(0xffffffffu, bd, off);
            int   ok = __shfl_xor_sync(0xffffffffu, bk, off);
            if (od < bd || (od == bd && ok < bk)) { bd = od; bk = ok; }
        }
        if (tx == 0) {
            int nl = (i < 4) ? (ty * 4 + i) : (64 + ty * 4 + (i - 4));
            idx_s[nl] = bk;
            atomicAdd(&g_counts[bk], 1);
            if (idxout) idxout[n0 + nl] = (float)bk;
        }
    }
    __syncthreads();

    // gather quantized rows into Qs[d][n]
    for (int i = tid; i < 2048; i += 256) {
        int db = i >> 7, nn = i & 127;
        float4 v = ((const float4*)cb)[idx_s[nn] * 16 + db];
        int d0 = db * 4;
        Qs[(d0 + 0) * 128 + nn] = v.x;
        Qs[(d0 + 1) * 128 + nn] = v.y;
        Qs[(d0 + 2) * 128 + nn] = v.z;
        Qs[(d0 + 3) * 128 + nn] = v.w;
    }
    for (int i = tid; i < 2048; i += 256) ((float4*)Es)[i] = ((const float4*)g_pt)[i];
    __syncthreads();

    // loss partial + straight-through: qst = fl(z + fl(q - z)) overwrites Qs
    float ls = 0.f;
    for (int i = tid; i < 8192; i += 256) {
        float z = Zs[i], q = Qs[i];
        float df = __fsub_rn(q, z);
        ls = fmaf(df, df, ls);
        Qs[i] = __fadd_rn(z, df);
    }
    #pragma unroll
    for (int off = 16; off > 0; off >>= 1) ls += __shfl_xor_sync(0xffffffffu, ls, off);
    if ((tid & 31) == 0) atomicAdd(&g_sumsq, ls);
    __syncthreads();

    // post GEMM on qst, serial-d FFMA chain
    ull acc2[4][8];
    #pragma unroll
    for (int ip = 0; ip < 4; ip++)
        #pragma unroll
        for (int j = 0; j < 8; j++) acc2[ip][j] = 0ULL;

    #pragma unroll 4
    for (int d = 0; d < EMB; d++) {
        ulonglong2 q0 = *(const ulonglong2*)(Qs + d * 128 + tx * 4);
        ulonglong2 q1 = *(const ulonglong2*)(Qs + d * 128 + 64 + tx * 4);
        float4 p0 = ((float4*)Es)[d * 32 + ty];
        float4 p1 = ((float4*)Es)[d * 32 + 16 + ty];
        ull qp[4] = {q0.x, q0.y, q1.x, q1.y};
        ull pd[8] = {dup2(p0.x), dup2(p0.y), dup2(p0.z), dup2(p0.w),
                     dup2(p1.x), dup2(p1.y), dup2(p1.z), dup2(p1.w)};
        #pragma unroll
        for (int ip = 0; ip < 4; ip++)
            #pragma unroll
            for (int j = 0; j < 8; j++)
                ffma2(acc2[ip][j], qp[ip], pd[j]);
    }

    // dec is 4B-aligned only (out + 1 float) -> scalar stores
    size_t base = (size_t)b * 524288 + hw0;
    #pragma unroll
    for (int j = 0; j < 8; j++) {
        int o = (j < 4) ? (ty * 4 + j) : (64 + ty * 4 + (j - 4));
        float ob = __ldg(post_b + o);
        float* p0 = dec + base + (size_t)o * 4096 + tx * 4;
        float2 r0 = unpack2(acc2[0][j]), r1 = unpack2(acc2[1][j]);
        p0[0] = __fadd_rn(r0.x, ob); p0[1] = __fadd_rn(r0.y, ob);
        p0[2] = __fadd_rn(r1.x, ob); p0[3] = __fadd_rn(r1.y, ob);
        float* p1 = p0 + 64;
        float2 r2 = unpack2(acc2[2][j]), r3 = unpack2(acc2[3][j]);
        p1[0] = __fadd_rn(r2.x, ob); p1[1] = __fadd_rn(r2.y, ob);
        p1[2] = __fadd_rn(r3.x, ob); p1[3] = __fadd_rn(r3.y, ob);
    }
}

// ---------------- finalize: loss + perplexity scalars ----------------
__global__ void vq_fin(float* __restrict__ loss_out, float* __restrict__ perp_out) {
    __shared__ float red[512];
    int t = threadIdx.x;
    float a = (float)g_counts[t] * (1.0f / 131072.0f);
    red[t] = a * logf(a + 1e-10f);
    __syncthreads();
    for (int s = 256; s > 0; s >>= 1) {
        if (t < s) red[t] += red[t + s];
        __syncthreads();
    }
    if (t == 0) {
        perp_out[0] = expf(-red[0]);
        loss_out[0] = 1.25f * g_sumsq * (1.0f / 8388608.0f);
    }
}

// ---------------- launch ----------------
extern "C" void kernel_launch(void* const* d_in, const int* in_sizes, int n_in,
                              void* d_out, int out_size) {
    const float* enc    = (const float*)d_in[0];
    const float* pre_w  = (const float*)d_in[1];
    const float* pre_b  = (const float*)d_in[2];
    const float* cb     = (const float*)d_in[3];
    const float* post_w = (const float*)d_in[4];
    const float* post_b = (const float*)d_in[5];
    float* out = (float*)d_out;

    const int DEC = 32 * 128 * 64 * 64;
    int full = (out_size >= DEC + 2 + NPOS) ? 1 : 0;
    float* p_loss = full ? out : nullptr;
    float* p_dec  = full ? (out + 1) : out;
    float* p_perp = full ? (out + 1 + DEC) : nullptr;
    float* p_idx  = full ? (out + 2 + DEC) : nullptr;

    const int PRE_SM  = (16384 + 8192) * 4;                  // 98304 B
    const int MAIN_SM = (8192 * 3 + 512 + 128 + 128) * 4;    // 101376 B
    cudaFuncSetAttribute(vq_pre,  cudaFuncAttributeMaxDynamicSharedMemorySize, PRE_SM);
    cudaFuncSetAttribute(vq_main, cudaFuncAttributeMaxDynamicSharedMemorySize, MAIN_SM);

    vq_init<<<64, 256>>>(pre_w, post_w, cb);
    vq_pre<<<NPOS / 128, 256, PRE_SM>>>(enc, pre_b);
    vq_norms<<<4096 + 32, 256>>>(cb);
    vq_main<<<NPOS / 128, 256, MAIN_SM>>>(cb, post_b, p_dec, p_idx);
    if (full) vq_fin<<<1, 512>>>(p_loss, p_perp);
}

// round 7
// speedup vs baseline: 1.1765x; 1.1765x over previous
#include <cuda_runtime.h>
#include <cstdint>
#include <cstddef>

// ---------------------------------------------------------------------------
// VQ-VAE bottleneck, GB300 sm_103a — fully fused version.
// B=32, C=128, H=W=64 -> N=131072 positions, D=64, K=512 codes.
// Bit-replicates fp32 reference numerics (validated in R3, rel_err 5e-7):
//   - GEMMs: serial-k FFMA chains (acc=0, ascending k)
//   - row norms: warp tree (x_l^2 + x_{l+32}^2, shfl_down 16..1)
//   - dists = fl(fl(A+B) - 2*M), argmin lexicographic (tie -> lowest index)
//   - straight-through: qst = fl(z + fl(q - z)) feeds the post conv
// One fused kernel does pre-conv -> norms -> distances -> argmin -> post-conv
// per 128-position tile entirely in shared memory (no z round-trip to DRAM).
// __launch_bounds__(256,2): 2 CTAs/SM (regs<=128, 2x101KB smem <= 228KB).
// ---------------------------------------------------------------------------

#define NPOS   131072
#define EMB    64
#define NCODE  512
#define NHID   128

__device__ __align__(16) float g_wt[NHID * EMB];   // pre_w  transposed: [c][o]
__device__ __align__(16) float g_pt[EMB * NHID];   // post_w transposed: [d][o]
__device__ __align__(16) float g_ct[EMB * NCODE];  // codebook transposed: [d][k]
__device__ float g_norm[NCODE];                    // ||e_k||^2 (warp tree)
__device__ int   g_counts[NCODE];
__device__ float g_sumsq;

typedef unsigned long long ull;

__device__ __forceinline__ void ffma2(ull &d, const ull a, const ull b) {
    asm("fma.rn.f32x2 %0, %1, %2, %0;" : "+l"(d) : "l"(a), "l"(b));
}
__device__ __forceinline__ ull dup2(float v) {
    ull r; unsigned int u = __float_as_uint(v);
    asm("mov.b64 %0, {%1, %1};" : "=l"(r) : "r"(u));
    return r;
}
__device__ __forceinline__ float2 unpack2(ull p) {
    float2 f;
    asm("mov.b64 {%0, %1}, %2;" : "=f"(f.x), "=f"(f.y) : "l"(p));
    return f;
}

// ---------------- init: transposes + codebook norms + zeroing ----------------
__global__ void __launch_bounds__(256) vq_init(const float* __restrict__ pre_w,
                                               const float* __restrict__ post_w,
                                               const float* __restrict__ cb) {
    int g = blockIdx.x * blockDim.x + threadIdx.x;
    int gs = gridDim.x * blockDim.x;
    for (int i = g; i < NHID * EMB; i += gs) {          // wt[c][o] = pre_w[o][c]
        int k = i >> 6, o = i & 63;
        g_wt[i] = pre_w[o * NHID + k];
    }
    for (int i = g; i < EMB * NHID; i += gs) {          // pt[d][o] = post_w[o][d]
        int d = i >> 7, o = i & 127;
        g_pt[i] = post_w[o * EMB + d];
    }
    for (int i = g; i < EMB * NCODE; i += gs) {         // ct[d][k] = cb[k][d]
        int d = i >> 9, k = i & 511;
        g_ct[i] = cb[k * EMB + d];
    }
    for (int i = g; i < NCODE; i += gs) g_counts[i] = 0;
    if (g == 0) g_sumsq = 0.f;

    // codebook norms: one warp per code, exact warp-tree
    int w = threadIdx.x >> 5, l = threadIdx.x & 31;
    int k = blockIdx.x * 8 + w;                          // grid=64 -> k in [0,512)
    float x = cb[k * 64 + l];
    float y = cb[k * 64 + l + 32];
    float p = __fadd_rn(__fmul_rn(x, x), __fmul_rn(y, y));
    #pragma unroll
    for (int s = 16; s > 0; s >>= 1)
        p = __fadd_rn(p, __shfl_down_sync(0xffffffffu, p, s));
    if (l == 0) g_norm[k] = p;
}

// ---------------- fused: pre conv + norms + dists + argmin + post conv ----------------
// smem (floats): RA[16384]: As -> {Es[8192] | Qs[8192]};  RB[8192]: Ws -> Zs;
//                norms[512]; idx[128]; An[128]   => 25344 floats = 101376 B
__global__ void __launch_bounds__(256, 2) vq_fused(const float* __restrict__ enc,
                                                   const float* __restrict__ pre_b,
                                                   const float* __restrict__ cb,
                                                   const float* __restrict__ post_b,
                                                   float* __restrict__ dec,
                                                   float* __restrict__ idxout) {
    extern __shared__ float sm[];
    float* RA = sm;                    // 16384
    float* RB = sm + 16384;            // 8192
    float* norms_s = sm + 24576;       // 512
    int*   idx_s = (int*)(sm + 25088); // 128
    float* An_s = sm + 25216;          // 128

    float* As = RA;        // [128 c][128 n]
    float* Ws = RB;        // [128 c][64 o]
    float* Zs = RB;        // [64 d][128 n]   (after pre phase)
    float* Es = RA;        // [64 d][128 k]   (distance chunks; later Ps)
    float* Qs = RA + 8192; // [64 d][128 n]

    const int tid = threadIdx.x;
    const int tx = tid & 15, ty = tid >> 4;
    const int n0 = blockIdx.x * 128;
    const int b  = n0 >> 12;
    const int hw0 = n0 & 4095;

    // ---- phase 1: load enc tile + pre weights ----
    const float4* enc4 = (const float4*)enc;
    float4* As4 = (float4*)As;
    float4* Ws4 = (float4*)Ws;
    for (int i = tid; i < 4096; i += 256) {
        int c = i >> 5, x = i & 31;
        As4[i] = enc4[(size_t)(b * NHID + c) * 1024 + (hw0 >> 2) + x];
    }
    for (int i = tid; i < 2048; i += 256) Ws4[i] = ((const float4*)g_wt)[i];
    for (int i = tid; i < NCODE; i += 256) norms_s[i] = g_norm[i];
    __syncthreads();

    // ---- pre GEMM: z[o][n], serial-c FFMA chains (bit-exact order) ----
    {
        ull acc[4][4];
        #pragma unroll
        for (int i = 0; i < 4; i++)
            #pragma unroll
            for (int j = 0; j < 4; j++) acc[i][j] = 0ULL;

        #pragma unroll 4
        for (int k = 0; k < NHID; k++) {
            ulonglong2 a0 = *(const ulonglong2*)(As + k * 128 + tx * 4);
            ulonglong2 a1 = *(const ulonglong2*)(As + k * 128 + 64 + tx * 4);
            float4 w = Ws4[k * 16 + ty];
            ull ap[4] = {a0.x, a0.y, a1.x, a1.y};
            ull wd[4] = {dup2(w.x), dup2(w.y), dup2(w.z), dup2(w.w)};
            #pragma unroll
            for (int ip = 0; ip < 4; ip++)
                #pragma unroll
                for (int j = 0; j < 4; j++)
                    ffma2(acc[ip][j], ap[ip], wd[j]);
        }
        __syncthreads();   // Ws reads done -> RB becomes Zs

        #pragma unroll
        for (int j = 0; j < 4; j++) {
            int o = ty * 4 + j;
            float bias = __ldg(pre_b + o);
            float2 p0 = unpack2(acc[0][j]), p1 = unpack2(acc[1][j]);
            *(float4*)(Zs + o * 128 + tx * 4) =
                make_float4(__fadd_rn(p0.x, bias), __fadd_rn(p0.y, bias),
                            __fadd_rn(p1.x, bias), __fadd_rn(p1.y, bias));
            float2 p2 = unpack2(acc[2][j]), p3 = unpack2(acc[3][j]);
            *(float4*)(Zs + o * 128 + 64 + tx * 4) =
                make_float4(__fadd_rn(p2.x, bias), __fadd_rn(p2.y, bias),
                            __fadd_rn(p3.x, bias), __fadd_rn(p3.y, bias));
        }
    }
    __syncthreads();

    // ---- phase 2: row norms A[n], exact warp-tree ----
    {
        int w = tid >> 5, l = tid & 31;
        #pragma unroll
        for (int it = 0; it < 16; it++) {
            int nn = w + it * 8;
            float x = Zs[l * 128 + nn];
            float y = Zs[(l + 32) * 128 + nn];
            float p = __fadd_rn(__fmul_rn(x, x), __fmul_rn(y, y));
            #pragma unroll
            for (int s = 16; s > 0; s >>= 1)
                p = __fadd_rn(p, __shfl_down_sync(0xffffffffu, p, s));
            if (l == 0) An_s[nn] = p;
        }
    }
    __syncthreads();

    float an[8];
    #pragma unroll
    for (int m = 0; m < 8; m++)
        an[m] = An_s[(m < 4) ? (ty * 4 + m) : (64 + ty * 4 + (m - 4))];

    // ---- phase 3: distances + running argmin over 4 chunks of 128 codes ----
    float best[8];
    int bidx[8];
    #pragma unroll
    for (int i = 0; i < 8; i++) { best[i] = 3.4e38f; bidx[i] = 0; }

    for (int kk = 0; kk < 4; kk++) {
        __syncthreads();
        for (int i = tid; i < 2048; i += 256) {
            int d = i >> 5, x = i & 31;
            ((float4*)Es)[i] = ((const float4*)g_ct)[d * 128 + kk * 32 + x];
        }
        __syncthreads();

        ull acc[4][8];
        #pragma unroll
        for (int ip = 0; ip < 4; ip++)
            #pragma unroll
            for (int j = 0; j < 8; j++) acc[ip][j] = 0ULL;

        #pragma unroll 4
        for (int d = 0; d < EMB; d++) {
            ulonglong2 z0 = *(const ulonglong2*)(Zs + d * 128 + ty * 4);
            ulonglong2 z1 = *(const ulonglong2*)(Zs + d * 128 + 64 + ty * 4);
            float4 e0 = ((float4*)Es)[d * 32 + tx];
            float4 e1 = ((float4*)Es)[d * 32 + 16 + tx];
            ull zp[4] = {z0.x, z0.y, z1.x, z1.y};
            ull ed[8] = {dup2(e0.x), dup2(e0.y), dup2(e0.z), dup2(e0.w),
                         dup2(e1.x), dup2(e1.y), dup2(e1.z), dup2(e1.w)};
            #pragma unroll
            for (int ip = 0; ip < 4; ip++)
                #pragma unroll
                for (int j = 0; j < 8; j++)
                    ffma2(acc[ip][j], zp[ip], ed[j]);
        }

        // d = fl(fl(A + B) - 2*M)
        #pragma unroll
        for (int j = 0; j < 8; j++) {
            int k = kk * 128 + ((j < 4) ? (tx * 4 + j) : (64 + tx * 4 + j - 4));
            float Bk = norms_s[k];
            #pragma unroll
            for (int ip = 0; ip < 4; ip++) {
                float2 dd = unpack2(acc[ip][j]);
                int i0 = ip * 2;
                float dv0 = __fsub_rn(__fadd_rn(an[i0], Bk), __fmul_rn(2.0f, dd.x));
                if (dv0 < best[i0]) { best[i0] = dv0; bidx[i0] = k; }
                float dv1 = __fsub_rn(__fadd_rn(an[i0 + 1], Bk), __fmul_rn(2.0f, dd.y));
                if (dv1 < best[i0 + 1]) { best[i0 + 1] = dv1; bidx[i0 + 1] = k; }
            }
        }
    }

    // ---- argmin across the 16 tx lanes sharing each row (tie -> lowest k) ----
    #pragma unroll
    for (int i = 0; i < 8; i++) {
        float bd = best[i]; int bk = bidx[i];
        #pragma unroll
        for (int off = 1; off < 16; off <<= 1) {
            float od = __shfl_xor_sync(0xffffffffu, bd, off);
            int   ok = __shfl_xor_sync(0xffffffffu, bk, off);
            if (od < bd || (od == bd && ok < bk)) { bd = od; bk = ok; }
        }
        if (tx == 0) {
            int nl = (i < 4) ? (ty * 4 + i) : (64 + ty * 4 + (i - 4));
            idx_s[nl] = bk;
            atomicAdd(&g_counts[bk], 1);
            if (idxout) idxout[n0 + nl] = (float)bk;
        }
    }
    __syncthreads();

    // ---- phase 4: gather quantized rows + load post weights ----
    for (int i = tid; i < 2048; i += 256) {
        int db = i >> 7, nn = i & 127;
        float4 v = ((const float4*)cb)[idx_s[nn] * 16 + db];
        int d0 = db * 4;
        Qs[(d0 + 0) * 128 + nn] = v.x;
        Qs[(d0 + 1) * 128 + nn] = v.y;
        Qs[(d0 + 2) * 128 + nn] = v.z;
        Qs[(d0 + 3) * 128 + nn] = v.w;
    }
    for (int i = tid; i < 2048; i += 256) ((float4*)Es)[i] = ((const float4*)g_pt)[i];
    __syncthreads();

    // ---- loss partial + straight-through qst = fl(z + fl(q - z)) ----
    float ls = 0.f;
    for (int i = tid; i < 8192; i += 256) {
        float z = Zs[i], q = Qs[i];
        float df = __fsub_rn(q, z);
        ls = fmaf(df, df, ls);
        Qs[i] = __fadd_rn(z, df);
    }
    #pragma unroll
    for (int off = 16; off > 0; off >>= 1) ls += __shfl_xor_sync(0xffffffffu, ls, off);
    if ((tid & 31) == 0) atomicAdd(&g_sumsq, ls);
    __syncthreads();

    // ---- phase 5: post GEMM on qst, serial-d FFMA chains ----
    ull acc2[4][8];
    #pragma unroll
    for (int ip = 0; ip < 4; ip++)
        #pragma unroll
        for (int j = 0; j < 8; j++) acc2[ip][j] = 0ULL;

    #pragma unroll 4
    for (int d = 0; d < EMB; d++) {
        ulonglong2 q0 = *(const ulonglong2*)(Qs + d * 128 + tx * 4);
        ulonglong2 q1 = *(const ulonglong2*)(Qs + d * 128 + 64 + tx * 4);
        float4 p0 = ((float4*)Es)[d * 32 + ty];
        float4 p1 = ((float4*)Es)[d * 32 + 16 + ty];
        ull qp[4] = {q0.x, q0.y, q1.x, q1.y};
        ull pd[8] = {dup2(p0.x), dup2(p0.y), dup2(p0.z), dup2(p0.w),
                     dup2(p1.x), dup2(p1.y), dup2(p1.z), dup2(p1.w)};
        #pragma unroll
        for (int ip = 0; ip < 4; ip++)
            #pragma unroll
            for (int j = 0; j < 8; j++)
                ffma2(acc2[ip][j], qp[ip], pd[j]);
    }

    // dec is 4B-aligned only (out + 1 float) -> scalar stores
    size_t base = (size_t)b * 524288 + hw0;
    #pragma unroll
    for (int j = 0; j < 8; j++) {
        int o = (j < 4) ? (ty * 4 + j) : (64 + ty * 4 + (j - 4));
        float ob = __ldg(post_b + o);
        float* p0 = dec + base + (size_t)o * 4096 + tx * 4;
        float2 r0 = unpack2(acc2[0][j]), r1 = unpack2(acc2[1][j]);
        p0[0] = __fadd_rn(r0.x, ob); p0[1] = __fadd_rn(r0.y, ob);
        p0[2] = __fadd_rn(r1.x, ob); p0[3] = __fadd_rn(r1.y, ob);
        float* p1 = p0 + 64;
        float2 r2 = unpack2(acc2[2][j]), r3 = unpack2(acc2[3][j]);
        p1[0] = __fadd_rn(r2.x, ob); p1[1] = __fadd_rn(r2.y, ob);
        p1[2] = __fadd_rn(r3.x, ob); p1[3] = __fadd_rn(r3.y, ob);
    }
}

// ---------------- finalize: loss + perplexity scalars ----------------
__global__ void vq_fin(float* __restrict__ loss_out, float* __restrict__ perp_out) {
    __shared__ float red[512];
    int t = threadIdx.x;
    float a = (float)g_counts[t] * (1.0f / 131072.0f);
    red[t] = a * logf(a + 1e-10f);
    __syncthreads();
    for (int s = 256; s > 0; s >>= 1) {
        if (t < s) red[t] += red[t + s];
        __syncthreads();
    }
    if (t == 0) {
        perp_out[0] = expf(-red[0]);
        loss_out[0] = 1.25f * g_sumsq * (1.0f / 8388608.0f);
    }
}

// ---------------- launch ----------------
extern "C" void kernel_launch(void* const* d_in, const int* in_sizes, int n_in,
                              void* d_out, int out_size) {
    const float* enc    = (const float*)d_in[0];
    const float* pre_w  = (const float*)d_in[1];
    const float* pre_b  = (const float*)d_in[2];
    const float* cb     = (const float*)d_in[3];
    const float* post_w = (const float*)d_in[4];
    const float* post_b = (const float*)d_in[5];
    float* out = (float*)d_out;

    const int DEC = 32 * 128 * 64 * 64;
    int full = (out_size >= DEC + 2 + NPOS) ? 1 : 0;
    float* p_loss = full ? out : nullptr;
    float* p_dec  = full ? (out + 1) : out;
    float* p_perp = full ? (out + 1 + DEC) : nullptr;
    float* p_idx  = full ? (out + 2 + DEC) : nullptr;

    const int FUSED_SM = 25344 * 4;   // 101376 B
    cudaFuncSetAttribute(vq_fused, cudaFuncAttributeMaxDynamicSharedMemorySize, FUSED_SM);

    vq_init<<<64, 256>>>(pre_w, post_w, cb);
    vq_fused<<<NPOS / 128, 256, FUSED_SM>>>(enc, pre_b, cb, post_b, p_dec, p_idx);
    if (full) vq_fin<<<1, 512>>>(p_loss, p_perp);
}